// round 5
// baseline (speedup 1.0000x reference)
#include <cuda_runtime.h>
#include <cuda_bf16.h>

// One-hot: x [8,1024] int32 -> out [8,1024,32000] fp32 (1.048 GB of stores).
// Single-wave persistent fill: 1216 blocks (152 SMs x 8, 2048 thr/SM) each
// own one contiguous float4 range (53,894 or 53,895 slots; imbalance = 1
// store). No wave transitions, no per-tile block churn. Each range spans
// <= 8 rows; x values are prefetched before the store stream so the LDG
// latency overlaps the fill. The hot-lane overwrite is done by the same
// thread that zeroed that slot ((s - lo) % 256 == tid), so same-thread
// same-address ordering guarantees correctness with no fence.

static constexpr int       NUM_CLASS = 32000;
static constexpr int       NC4       = NUM_CLASS / 4;        // 8000 float4/row
static constexpr long long TOTAL_F4  = 8LL * 1024 * NC4;     // 65,536,000
static constexpr int       BLOCKS    = 152 * 8;              // 1216 — one wave
static constexpr int       THREADS   = 256;

__global__ void __launch_bounds__(THREADS, 8)
onehot_persist_kernel(const int* __restrict__ x, float4* __restrict__ out)
{
    const int bid = blockIdx.x;
    const int tid = threadIdx.x;

    const long long Q = TOTAL_F4 / BLOCKS;            // 53,894
    const int       R = (int)(TOTAL_F4 % BLOCKS);     // 896
    const long long lo = (long long)bid * Q + (bid < R ? bid : R);
    const long long n  = Q + (bid < R ? 1 : 0);
    const long long hi = lo + n;

    // Prefetch the x values for every row this range touches (<= 8 rows),
    // so the loads are in flight while we stream zeros.
    const int r0 = (int)(lo / NC4);
    const int r1 = (int)((hi - 1) / NC4);
    int tvals[8];
#pragma unroll
    for (int k = 0; k < 8; ++k) {
        if (r0 + k <= r1) tvals[k] = __ldg(x + r0 + k);
    }

    float4* p = out + lo;
    const float4 z = make_float4(0.f, 0.f, 0.f, 0.f);

    long long i = tid;
    for (; i + 7 * THREADS < n; i += 8 * THREADS) {
#pragma unroll
        for (int u = 0; u < 8; ++u)
            __stcs(p + i + u * THREADS, z);           // evict-first streaming
    }
    for (; i < n; i += THREADS)
        __stcs(p + i, z);

    // Hot-lane overwrites for rows overlapping [lo, hi). Exactly one block
    // contains each hot slot; within it, the zeroing thread does the write.
#pragma unroll
    for (int k = 0; k < 8; ++k) {
        const int r = r0 + k;
        if (r > r1) break;
        const int t = tvals[k];
        const long long s = (long long)r * NC4 + (t >> 2);
        if (s >= lo && s < hi && (int)((s - lo) & (THREADS - 1)) == tid) {
            reinterpret_cast<float*>(p + (s - lo))[t & 3] = 1.0f;
        }
    }
}

extern "C" void kernel_launch(void* const* d_in, const int* in_sizes, int n_in,
                              void* d_out, int out_size)
{
    const int* x = (const int*)d_in[0];
    onehot_persist_kernel<<<BLOCKS, THREADS>>>(x, (float4*)d_out);
}

// round 6
// speedup vs baseline: 1.2314x; 1.2314x over previous
#include <cuda_runtime.h>
#include <cuda_bf16.h>

// One-hot: x [8,1024] int32 -> out [8,1024,32000] fp32 (1.048 GB).
// Probe: let the driver's memset path (graph memset node, potentially the
// copy-engine fill hardware) do the 1 GB zero-fill instead of SM STG
// instructions, then scatter the 8192 ones with a tiny kernel. Stream
// ordering (same capture stream) orders scatter after memset.

static constexpr int NUM_CLASS = 32000;
static constexpr int ROWS      = 8 * 1024;   // 8192

__global__ void __launch_bounds__(256)
scatter_ones_kernel(const int* __restrict__ x, float* __restrict__ out)
{
    const int row = blockIdx.x * 256 + threadIdx.x;
    if (row < ROWS) {
        const int t = __ldg(x + row);
        out[(long long)row * NUM_CLASS + t] = 1.0f;
    }
}

extern "C" void kernel_launch(void* const* d_in, const int* in_sizes, int n_in,
                              void* d_out, int out_size)
{
    const int* x = (const int*)d_in[0];

    // Graph-capturable: becomes a memset node in the captured graph.
    cudaMemsetAsync(d_out, 0, (size_t)out_size * sizeof(float));

    scatter_ones_kernel<<<(ROWS + 255) / 256, 256>>>(x, (float*)d_out);
}

// round 7
// speedup vs baseline: 1.2635x; 1.0261x over previous
#include <cuda_runtime.h>
#include <cuda_bf16.h>

// One-hot: x [8,1024] int32 -> out [8,1024,32000] fp32 (1.048 GB of stores).
// Fused quarter-row blocks: grid = 32768 (4 per row), 256 threads, 2000
// float4 per block = 7 full iters + 208-thread tail. Finer granularity
// -> ~27 waves -> the final partial wave strands SMs for ~0.5 us instead
// of ~5 us (this was the measurable gain from R2 -> R3; push it further).
// The 1.0f overwrite is done by the same thread that zeroed that slot
// (owner tid == o & 255), so same-thread same-address ordering applies.

static constexpr int NUM_CLASS = 32000;
static constexpr int NC4       = NUM_CLASS / 4;    // 8000 float4 per row
static constexpr int ROWS      = 8 * 1024;         // 8192
static constexpr int QUART     = NC4 / 4;          // 2000 float4 per block
static constexpr int THREADS   = 256;
static constexpr int FULL_IT   = QUART / THREADS;  // 7
static constexpr int TAIL      = QUART - FULL_IT * THREADS;  // 208

__global__ void __launch_bounds__(THREADS)
onehot_quarter_kernel(const int* __restrict__ x, float4* __restrict__ out)
{
    const int row = blockIdx.x >> 2;
    const int q   = blockIdx.x & 3;
    const int tid = threadIdx.x;

    const int t = __ldg(x + row);                  // issued early; stores don't wait

    float4* p = out + (long long)row * NC4 + q * QUART;
    const float4 z = make_float4(0.f, 0.f, 0.f, 0.f);

#pragma unroll
    for (int i = 0; i < FULL_IT; ++i) {
        __stcs(p + i * THREADS + tid, z);          // evict-first streaming store
    }
    if (tid < TAIL) {
        __stcs(p + FULL_IT * THREADS + tid, z);
    }

    // hot-slot overwrite: offset of the hot float4 within this quarter-row
    const int o = (t >> 2) - q * QUART;
    if (o >= 0 && o < QUART && (o & (THREADS - 1)) == tid) {
        reinterpret_cast<float*>(p + o)[t & 3] = 1.0f;  // same thread zeroed p[o]
    }
}

extern "C" void kernel_launch(void* const* d_in, const int* in_sizes, int n_in,
                              void* d_out, int out_size)
{
    const int* x = (const int*)d_in[0];
    onehot_quarter_kernel<<<ROWS * 4, THREADS>>>(x, (float4*)d_out);
}

// round 8
// speedup vs baseline: 1.2679x; 1.0034x over previous
#include <cuda_runtime.h>
#include <cuda_bf16.h>

// One-hot: x [8,1024] int32 -> out [8,1024,32000] fp32 (1.048 GB of stores).
// Fused eighth-row blocks: grid = 65536 (8 per row), 256 threads, 1000
// float4 per block = 3 full iters + 232-thread tail. Granularity curve so
// far (kernel time): full-row 141.1 -> half 139.6 -> quarter 137.0 us; each
// halving shrinks last-wave/imbalance idle. The 1.0f overwrite is done by
// the same thread that zeroed that slot (tid == o & 255), so same-thread
// same-address ordering guarantees the final value with no fence.

static constexpr int NUM_CLASS = 32000;
static constexpr int NC4       = NUM_CLASS / 4;    // 8000 float4 per row
static constexpr int ROWS      = 8 * 1024;         // 8192
static constexpr int CHUNK     = NC4 / 8;          // 1000 float4 per block
static constexpr int THREADS   = 256;
static constexpr int FULL_IT   = CHUNK / THREADS;  // 3
static constexpr int TAIL      = CHUNK - FULL_IT * THREADS;  // 232

__global__ void __launch_bounds__(THREADS)
onehot_eighth_kernel(const int* __restrict__ x, float4* __restrict__ out)
{
    const int row = blockIdx.x >> 3;
    const int c   = blockIdx.x & 7;
    const int tid = threadIdx.x;

    const int t = __ldg(x + row);                  // broadcast; stores don't wait

    float4* p = out + (long long)row * NC4 + c * CHUNK;
    const float4 z = make_float4(0.f, 0.f, 0.f, 0.f);

#pragma unroll
    for (int i = 0; i < FULL_IT; ++i) {
        __stcs(p + i * THREADS + tid, z);          // evict-first streaming store
    }
    if (tid < TAIL) {
        __stcs(p + FULL_IT * THREADS + tid, z);
    }

    // hot-slot overwrite: offset of the hot float4 within this chunk
    const int o = (t >> 2) - c * CHUNK;
    if (o >= 0 && o < CHUNK && (o & (THREADS - 1)) == tid) {
        reinterpret_cast<float*>(p + o)[t & 3] = 1.0f;  // same thread zeroed p[o]
    }
}

extern "C" void kernel_launch(void* const* d_in, const int* in_sizes, int n_in,
                              void* d_out, int out_size)
{
    const int* x = (const int*)d_in[0];
    onehot_eighth_kernel<<<ROWS * 8, THREADS>>>(x, (float4*)d_out);
}